// round 7
// baseline (speedup 1.0000x reference)
#include <cuda_runtime.h>
#include <cuda_bf16.h>
#include <math.h>
#include <stdint.h>

#define N_NODES  100000
#define N_EDGES  3200000
#define HID      128
#define N_GRAPHS 512
#define N_CLASSES 10
#define BN_EPS   1e-5f

// ---------------- scratch (device globals; no allocations) ----------------
__device__ float g_h[N_NODES * HID];
__device__ float g_z[N_NODES * HID];
__device__ int   g_deg[N_NODES];
__device__ int   g_off[N_NODES + 1];
__device__ int   g_cur[N_NODES];
__device__ int   g_csr[N_EDGES];
__device__ float g_pool[N_GRAPHS * HID];
__device__ float g_cnt[N_GRAPHS];

#define STR   136                      // bf16 row stride (272B, 16B-aligned rows)
#define WT_ELEMS (HID * STR)
__device__ __nv_bfloat16 g_whi[3 * 2 * WT_ELEMS];
__device__ __nv_bfloat16 g_wlo[3 * 2 * WT_ELEMS];

// ---------------- CSR build ----------------
__global__ void k_zero() {
    int i = blockIdx.x * blockDim.x + threadIdx.x;
    if (i < N_NODES) g_deg[i] = 0;
    if (i < N_GRAPHS * HID) g_pool[i] = 0.0f;
    if (i < N_GRAPHS) g_cnt[i] = 0.0f;
}

__global__ void k_hist(const int* __restrict__ dst) {
    int e = blockIdx.x * blockDim.x + threadIdx.x;
    if (e < N_EDGES) atomicAdd(&g_deg[dst[e]], 1);
}

__global__ void k_scan() {
    __shared__ int warpsum[32];
    const int tid = threadIdx.x;
    const int C = (N_NODES + 1023) / 1024;
    const int beg = tid * C;
    const int end = min(beg + C, N_NODES);
    int sum = 0;
    for (int i = beg; i < end; i++) sum += g_deg[i];
    int lane = tid & 31, wid = tid >> 5;
    int v = sum;
#pragma unroll
    for (int d = 1; d < 32; d <<= 1) {
        int t = __shfl_up_sync(0xffffffffu, v, d);
        if (lane >= d) v += t;
    }
    if (lane == 31) warpsum[wid] = v;
    __syncthreads();
    if (wid == 0) {
        int w = warpsum[lane];
#pragma unroll
        for (int d = 1; d < 32; d <<= 1) {
            int t = __shfl_up_sync(0xffffffffu, w, d);
            if (lane >= d) w += t;
        }
        warpsum[lane] = w;
    }
    __syncthreads();
    int excl = v - sum + (wid > 0 ? warpsum[wid - 1] : 0);
    int run = excl;
    for (int i = beg; i < end; i++) {
        int d = g_deg[i];
        g_off[i] = run;
        g_cur[i] = run;
        run += d;
    }
    if (tid == 1023) g_off[N_NODES] = run;
}

__global__ void k_scatter(const int* __restrict__ src, const int* __restrict__ dst) {
    int e = blockIdx.x * blockDim.x + threadIdx.x;
    if (e < N_EDGES) {
        int pos = atomicAdd(&g_cur[dst[e]], 1);
        g_csr[pos] = src[e];
    }
}

// ---------------- weight pre-split (once per call) ----------------
__global__ void k_wsplit(const float* __restrict__ W1, const float* __restrict__ W2) {
    int i = blockIdx.x * blockDim.x + threadIdx.x;   // over 3*2*16384
    if (i >= 3 * 2 * HID * HID) return;
    int l = i / (2 * HID * HID);
    int rem = i % (2 * HID * HID);
    int m = rem / (HID * HID);
    int kn = rem % (HID * HID);
    int k = kn >> 7, n = kn & 127;
    float v = (m ? W2 : W1)[l * HID * HID + kn];
    __nv_bfloat16 hb = __float2bfloat16(v);
    __nv_bfloat16 lb = __float2bfloat16(v - __bfloat162float(hb));
    int o = (l * 2 + m) * WT_ELEMS + k * STR + n;
    g_whi[o] = hb;
    g_wlo[o] = lb;
}

// ---------------- fused GIN layer ----------------
#define T_BYTES (HID * STR * 2)        // 34816 per tile
#define OFF_AHI 0
#define OFF_ALO (T_BYTES)
#define OFF_BHI (2 * T_BYTES)
#define OFF_BLO (3 * T_BYTES)
#define SMEM_GIN (4 * T_BYTES)

__device__ __forceinline__ uint32_t smem_u32(const void* p) {
    uint32_t a;
    asm("{ .reg .u64 t; cvta.to.shared.u64 t, %1; cvt.u32.u64 %0, t; }" : "=r"(a) : "l"(p));
    return a;
}

__device__ __forceinline__ void pack2(float v0, float v1, uint32_t& hi, uint32_t& lo) {
    uint32_t h;
    asm("cvt.rn.bf16x2.f32 %0, %1, %2;" : "=r"(h) : "f"(v1), "f"(v0));
    float h0 = __uint_as_float(h << 16);
    float h1 = __uint_as_float(h & 0xffff0000u);
    asm("cvt.rn.bf16x2.f32 %0, %1, %2;" : "=r"(lo) : "f"(v1 - h1), "f"(v0 - h0));
    hi = h;
}

#define LDSM_X4(r0, r1, r2, r3, a)                                                 \
    asm volatile("ldmatrix.sync.aligned.m8n8.x4.shared.b16 {%0,%1,%2,%3}, [%4];"   \
        : "=r"(r0), "=r"(r1), "=r"(r2), "=r"(r3) : "r"(a))
#define LDSM_X4T(r0, r1, r2, r3, a)                                                \
    asm volatile("ldmatrix.sync.aligned.m8n8.x4.trans.shared.b16 {%0,%1,%2,%3}, [%4];" \
        : "=r"(r0), "=r"(r1), "=r"(r2), "=r"(r3) : "r"(a))
#define MMA16816(d, a, b0, b1)                                                     \
    asm volatile("mma.sync.aligned.m16n8k16.row.col.f32.bf16.bf16.f32 "            \
        "{%0,%1,%2,%3},{%4,%5,%6,%7},{%8,%9},{%0,%1,%2,%3};"                       \
        : "+f"((d)[0]), "+f"((d)[1]), "+f"((d)[2]), "+f"((d)[3])                   \
        : "r"((a)[0]), "r"((a)[1]), "r"((a)[2]), "r"((a)[3]), "r"(b0), "r"(b1))

__device__ __forceinline__ void copy_W(char* smem, int widx, int tid) {
    const uint4* shi = (const uint4*)(g_whi + (size_t)widx * WT_ELEMS);
    const uint4* slo = (const uint4*)(g_wlo + (size_t)widx * WT_ELEMS);
    uint4* dhi = (uint4*)(smem + OFF_BHI);
    uint4* dlo = (uint4*)(smem + OFF_BLO);
    for (int i = tid; i < T_BYTES / 16; i += 512) {
        dhi[i] = shi[i];
        dlo[i] = slo[i];
    }
}

__device__ __forceinline__ void gemm_mma2(uint32_t sb, int warpR, int warpC,
                                          int lane, float acc[8][4]) {
    const int lr = lane & 7, lj = lane >> 3;
    const uint32_t aOff = (uint32_t)((warpR + ((lj & 1) << 3) + lr) * STR
                                     + ((lj >> 1) << 3)) * 2;
    const uint32_t bRowPart = (uint32_t)((((lj >> 1) << 3) + lr) * STR
                                         + warpC + ((lj & 1) << 3)) * 2;
#pragma unroll
    for (int kt = 0; kt < 8; kt++) {
        uint32_t ah[4], al[4];
        uint32_t aAddr = sb + OFF_AHI + aOff + kt * 32;
        LDSM_X4(ah[0], ah[1], ah[2], ah[3], aAddr);
        LDSM_X4(al[0], al[1], al[2], al[3], aAddr + (OFF_ALO - OFF_AHI));
        uint32_t bBase = sb + OFF_BHI + bRowPart + (uint32_t)(kt * 16 * STR) * 2;
#pragma unroll
        for (int q = 0; q < 4; q++) {
            uint32_t bh[4], bl[4];
            uint32_t bAddr = bBase + q * 32;
            LDSM_X4T(bh[0], bh[1], bh[2], bh[3], bAddr);
            LDSM_X4T(bl[0], bl[1], bl[2], bl[3], bAddr + (OFF_BLO - OFF_BHI));
            MMA16816(acc[2 * q],     ah, bh[0], bh[2]);
            MMA16816(acc[2 * q],     ah, bl[0], bl[2]);
            MMA16816(acc[2 * q],     al, bh[0], bh[2]);
            MMA16816(acc[2 * q + 1], ah, bh[1], bh[3]);
            MMA16816(acc[2 * q + 1], ah, bl[1], bl[3]);
            MMA16816(acc[2 * q + 1], al, bh[1], bh[3]);
        }
    }
}

__global__ void __launch_bounds__(512, 1)
k_gin_layer(const float* __restrict__ hin, float* __restrict__ hout, int layer,
            const float* __restrict__ b1, const float* __restrict__ b2,
            const float* __restrict__ gamma, const float* __restrict__ beta,
            const float* __restrict__ mu, const float* __restrict__ var,
            const float* __restrict__ epsp) {
    extern __shared__ __align__(16) char smem[];
    const uint32_t sb = smem_u32(smem);
    const int tid = threadIdx.x;
    const int warp = tid >> 5, lane = tid & 31;
    const int rowBase = blockIdx.x * 128;
    const float eps1 = 1.0f + epsp[layer];

    // phase 1: aggregate 8 nodes per warp, pack -> bf16 hi/lo A tile
    {
        const float4* hv = (const float4*)hin;
        for (int i = 0; i < 8; i++) {
            int nl = warp * 8 + i;
            int node = rowBase + nl;
            float4 acc = make_float4(0.f, 0.f, 0.f, 0.f);
            if (node < N_NODES) {
                int beg = g_off[node], end = g_off[node + 1];
                for (int base = beg; base < end; base += 32) {
                    int n = min(32, end - base);
                    int s = (lane < n) ? g_csr[base + lane] : 0;
#pragma unroll 4
                    for (int j = 0; j < n; j++) {
                        int sj = __shfl_sync(0xffffffffu, s, j);
                        float4 v = hv[sj * 32 + lane];
                        acc.x += v.x; acc.y += v.y; acc.z += v.z; acc.w += v.w;
                    }
                }
                float4 self = hv[node * 32 + lane];
                acc.x += eps1 * self.x; acc.y += eps1 * self.y;
                acc.z += eps1 * self.z; acc.w += eps1 * self.w;
            }
            uint32_t h01, l01, h23, l23;
            pack2(acc.x, acc.y, h01, l01);
            pack2(acc.z, acc.w, h23, l23);
            uint32_t boff = (uint32_t)(nl * STR + lane * 4) * 2;
            *(uint2*)(smem + OFF_AHI + boff) = make_uint2(h01, h23);
            *(uint2*)(smem + OFF_ALO + boff) = make_uint2(l01, l23);
        }
    }
    copy_W(smem, layer * 2 + 0, tid);       // W1
    __syncthreads();

    const int warpR = (warp >> 1) * 16;
    const int warpC = (warp & 1) * 64;
    float acc[8][4];
#pragma unroll
    for (int p = 0; p < 8; p++)
#pragma unroll
        for (int j = 0; j < 4; j++) acc[p][j] = 0.f;
    gemm_mma2(sb, warpR, warpC, lane, acc);
    __syncthreads();                        // GEMM1 reads done

    // mid epilogue: relu(acc + b1) -> own (row, col) region of A
    {
        const int r = lane >> 2, cB = (lane & 3) * 2;
        const int row0 = warpR + r, row1 = row0 + 8;
#pragma unroll
        for (int p = 0; p < 8; p++) {
            int c = warpC + p * 8 + cB;
            float2 bb = __ldg((const float2*)&b1[c]);
            uint32_t h, l;
            pack2(fmaxf(acc[p][0] + bb.x, 0.f), fmaxf(acc[p][1] + bb.y, 0.f), h, l);
            *(uint32_t*)(smem + OFF_AHI + (row0 * STR + c) * 2) = h;
            *(uint32_t*)(smem + OFF_ALO + (row0 * STR + c) * 2) = l;
            pack2(fmaxf(acc[p][2] + bb.x, 0.f), fmaxf(acc[p][3] + bb.y, 0.f), h, l);
            *(uint32_t*)(smem + OFF_AHI + (row1 * STR + c) * 2) = h;
            *(uint32_t*)(smem + OFF_ALO + (row1 * STR + c) * 2) = l;
        }
    }
    copy_W(smem, layer * 2 + 1, tid);       // W2
    __syncthreads();

#pragma unroll
    for (int p = 0; p < 8; p++)
#pragma unroll
        for (int j = 0; j < 4; j++) acc[p][j] = 0.f;
    gemm_mma2(sb, warpR, warpC, lane, acc);

    // final epilogue: bias2 + relu + BN -> hout
    {
        const int r = lane >> 2, cB = (lane & 3) * 2;
        const int gr0 = rowBase + warpR + r, gr1 = gr0 + 8;
#pragma unroll
        for (int p = 0; p < 8; p++) {
            int c = warpC + p * 8 + cB;
            float2 bb = __ldg((const float2*)&b2[c]);
            float2 gm = __ldg((const float2*)&gamma[c]);
            float2 vr = __ldg((const float2*)&var[c]);
            float2 mm = __ldg((const float2*)&mu[c]);
            float2 be = __ldg((const float2*)&beta[c]);
            float sc0 = gm.x * rsqrtf(vr.x + BN_EPS);
            float sc1 = gm.y * rsqrtf(vr.y + BN_EPS);
            float sh0 = be.x - mm.x * sc0;
            float sh1 = be.y - mm.y * sc1;
            if (gr0 < N_NODES) {
                float o0 = fmaxf(acc[p][0] + bb.x, 0.f) * sc0 + sh0;
                float o1 = fmaxf(acc[p][1] + bb.y, 0.f) * sc1 + sh1;
                *(float2*)&hout[(size_t)gr0 * HID + c] = make_float2(o0, o1);
            }
            if (gr1 < N_NODES) {
                float o0 = fmaxf(acc[p][2] + bb.x, 0.f) * sc0 + sh0;
                float o1 = fmaxf(acc[p][3] + bb.y, 0.f) * sc1 + sh1;
                *(float2*)&hout[(size_t)gr1 * HID + c] = make_float2(o0, o1);
            }
        }
    }
}

// ---------------- pooling ----------------
__global__ void k_pool(const int* __restrict__ batch) {
    int idx = blockIdx.x * blockDim.x + threadIdx.x;
    int node = idx >> 5, lane = idx & 31;
    if (node >= N_NODES) return;
    int b = batch[node];
    float4 v = ((const float4*)g_h)[node * 32 + lane];
    float* p = &g_pool[b * HID + lane * 4];
    atomicAdd(p + 0, v.x);
    atomicAdd(p + 1, v.y);
    atomicAdd(p + 2, v.z);
    atomicAdd(p + 3, v.w);
    if (lane == 0) atomicAdd(&g_cnt[b], 1.0f);
}

// ---------------- head ----------------
__global__ void k_head(const float* __restrict__ l1w, const float* __restrict__ l1b,
                       const float* __restrict__ l2w, const float* __restrict__ l2b,
                       float* __restrict__ out) {
    __shared__ float p[HID], q[HID], r[N_CLASSES];
    int g = blockIdx.x, tid = threadIdx.x;
    float cnt = fmaxf(g_cnt[g], 1.0f);
    p[tid] = g_pool[g * HID + tid] / cnt;
    __syncthreads();
    float acc = l1b[tid];
    for (int k = 0; k < HID; k++) acc += p[k] * l1w[k * HID + tid];
    q[tid] = fmaxf(acc, 0.f);
    __syncthreads();
    if (tid < N_CLASSES) {
        float a2 = l2b[tid];
        for (int k = 0; k < HID; k++) a2 += q[k] * l2w[k * N_CLASSES + tid];
        r[tid] = a2;
    }
    __syncthreads();
    if (tid < N_CLASSES) {
        float m = -INFINITY;
        for (int j = 0; j < N_CLASSES; j++) m = fmaxf(m, r[j]);
        float s = 0.f;
        for (int j = 0; j < N_CLASSES; j++) s += expf(r[j] - m);
        out[g * N_CLASSES + tid] = r[tid] - m - logf(s);
    }
}

// ---------------- launch ----------------
extern "C" void kernel_launch(void* const* d_in, const int* in_sizes, int n_in,
                              void* d_out, int out_size) {
    const float* x        = (const float*)d_in[0];
    const int*   eidx     = (const int*)d_in[1];
    const int*   batch    = (const int*)d_in[2];
    const float* W1       = (const float*)d_in[3];
    const float* b1       = (const float*)d_in[4];
    const float* W2       = (const float*)d_in[5];
    const float* b2       = (const float*)d_in[6];
    const float* gamma    = (const float*)d_in[7];
    const float* beta     = (const float*)d_in[8];
    const float* bn_mean  = (const float*)d_in[9];
    const float* bn_var   = (const float*)d_in[10];
    const float* eps      = (const float*)d_in[11];
    const float* lin1_w   = (const float*)d_in[12];
    const float* lin1_b   = (const float*)d_in[13];
    const float* lin2_w   = (const float*)d_in[14];
    const float* lin2_b   = (const float*)d_in[15];
    float* out = (float*)d_out;

    const int* src = eidx;
    const int* dst = eidx + N_EDGES;

    cudaFuncSetAttribute(k_gin_layer, cudaFuncAttributeMaxDynamicSharedMemorySize, SMEM_GIN);

    k_zero<<<(N_NODES + 255) / 256, 256>>>();
    k_hist<<<(N_EDGES + 255) / 256, 256>>>(dst);
    k_scan<<<1, 1024>>>();
    k_scatter<<<(N_EDGES + 255) / 256, 256>>>(src, dst);
    k_wsplit<<<(3 * 2 * HID * HID + 255) / 256, 256>>>(W1, W2);

    float *d_h = nullptr, *d_z = nullptr;
    cudaGetSymbolAddress((void**)&d_h, g_h);
    cudaGetSymbolAddress((void**)&d_z, g_z);

    const int nblk = (N_NODES + 127) / 128;
    const float* lin = x;
    // ping-pong: x -> g_h -> g_z -> g_h
    for (int l = 0; l < 3; l++) {
        float* lout = (l == 1) ? d_z : d_h;
        k_gin_layer<<<nblk, 512, SMEM_GIN>>>(
            lin, lout, l,
            b1 + l * HID, b2 + l * HID,
            gamma + l * HID, beta + l * HID,
            bn_mean + l * HID, bn_var + l * HID, eps);
        lin = lout;
    }

    k_pool<<<(N_NODES * 32 + 255) / 256, 256>>>(batch);
    k_head<<<N_GRAPHS, HID>>>(lin1_w, lin1_b, lin2_w, lin2_b, out);
}

// round 8
// speedup vs baseline: 1.1837x; 1.1837x over previous
#include <cuda_runtime.h>
#include <cuda_bf16.h>
#include <math.h>
#include <stdint.h>

#define N_NODES  100000
#define N_EDGES  3200000
#define HID      128
#define N_GRAPHS 512
#define N_CLASSES 10
#define BN_EPS   1e-5f

// ---------------- scratch (device globals; no allocations) ----------------
__device__ float g_h[N_NODES * HID];
__device__ __nv_bfloat16 g_zhi[N_NODES * HID];   // aggregated z, bf16 hi
__device__ __nv_bfloat16 g_zlo[N_NODES * HID];   // aggregated z, bf16 lo (residual)
__device__ int   g_deg[N_NODES];
__device__ int   g_off[N_NODES + 1];
__device__ int   g_cur[N_NODES];
__device__ int   g_csr[N_EDGES];
__device__ float g_pool[N_GRAPHS * HID];
__device__ float g_cnt[N_GRAPHS];

#define STR   136                      // bf16 row stride in smem (272B, 16B-aligned)
#define WT_ELEMS (HID * STR)
__device__ __nv_bfloat16 g_whi[3 * 2 * WT_ELEMS];
__device__ __nv_bfloat16 g_wlo[3 * 2 * WT_ELEMS];

// ---------------- CSR build ----------------
__global__ void k_zero() {
    int i = blockIdx.x * blockDim.x + threadIdx.x;
    if (i < N_NODES) g_deg[i] = 0;
    if (i < N_GRAPHS * HID) g_pool[i] = 0.0f;
    if (i < N_GRAPHS) g_cnt[i] = 0.0f;
}

__global__ void k_hist(const int* __restrict__ dst) {
    int e = blockIdx.x * blockDim.x + threadIdx.x;
    if (e < N_EDGES) atomicAdd(&g_deg[dst[e]], 1);
}

__global__ void k_scan() {
    __shared__ int warpsum[32];
    const int tid = threadIdx.x;
    const int C = (N_NODES + 1023) / 1024;
    const int beg = tid * C;
    const int end = min(beg + C, N_NODES);
    int sum = 0;
    for (int i = beg; i < end; i++) sum += g_deg[i];
    int lane = tid & 31, wid = tid >> 5;
    int v = sum;
#pragma unroll
    for (int d = 1; d < 32; d <<= 1) {
        int t = __shfl_up_sync(0xffffffffu, v, d);
        if (lane >= d) v += t;
    }
    if (lane == 31) warpsum[wid] = v;
    __syncthreads();
    if (wid == 0) {
        int w = warpsum[lane];
#pragma unroll
        for (int d = 1; d < 32; d <<= 1) {
            int t = __shfl_up_sync(0xffffffffu, w, d);
            if (lane >= d) w += t;
        }
        warpsum[lane] = w;
    }
    __syncthreads();
    int excl = v - sum + (wid > 0 ? warpsum[wid - 1] : 0);
    int run = excl;
    for (int i = beg; i < end; i++) {
        int d = g_deg[i];
        g_off[i] = run;
        g_cur[i] = run;
        run += d;
    }
    if (tid == 1023) g_off[N_NODES] = run;
}

__global__ void k_scatter(const int* __restrict__ src, const int* __restrict__ dst) {
    int e = blockIdx.x * blockDim.x + threadIdx.x;
    if (e < N_EDGES) {
        int pos = atomicAdd(&g_cur[dst[e]], 1);
        g_csr[pos] = src[e];
    }
}

// ---------------- bf16 split helpers ----------------
__device__ __forceinline__ void pack2(float v0, float v1, uint32_t& hi, uint32_t& lo) {
    uint32_t h;
    asm("cvt.rn.bf16x2.f32 %0, %1, %2;" : "=r"(h) : "f"(v1), "f"(v0));
    float h0 = __uint_as_float(h << 16);
    float h1 = __uint_as_float(h & 0xffff0000u);
    asm("cvt.rn.bf16x2.f32 %0, %1, %2;" : "=r"(lo) : "f"(v1 - h1), "f"(v0 - h0));
    hi = h;
}

// ---------------- weight pre-split (once per call) ----------------
__global__ void k_wsplit(const float* __restrict__ W1, const float* __restrict__ W2) {
    int i = blockIdx.x * blockDim.x + threadIdx.x;   // over 3*2*16384
    if (i >= 3 * 2 * HID * HID) return;
    int l = i / (2 * HID * HID);
    int rem = i % (2 * HID * HID);
    int m = rem / (HID * HID);
    int kn = rem % (HID * HID);
    int k = kn >> 7, n = kn & 127;
    float v = (m ? W2 : W1)[l * HID * HID + kn];
    __nv_bfloat16 hb = __float2bfloat16(v);
    __nv_bfloat16 lb = __float2bfloat16(v - __bfloat162float(hb));
    int o = (l * 2 + m) * WT_ELEMS + k * STR + n;
    g_whi[o] = hb;
    g_wlo[o] = lb;
}

// ---------------- aggregation: z packed to bf16 hi/lo ----------------
__global__ void k_agg(const float* __restrict__ x, int layer, const float* __restrict__ epsp) {
    int node = (blockIdx.x * blockDim.x + threadIdx.x) >> 5;
    int lane = threadIdx.x & 31;
    if (node >= N_NODES) return;
    const float* hin = (layer == 0) ? x : (const float*)g_h;
    const float4* hv = (const float4*)hin;
    int beg = g_off[node], end = g_off[node + 1];
    float4 acc = make_float4(0.f, 0.f, 0.f, 0.f);
    for (int base = beg; base < end; base += 32) {
        int n = min(32, end - base);
        int s = (lane < n) ? g_csr[base + lane] : 0;
#pragma unroll 4
        for (int j = 0; j < n; j++) {
            int sj = __shfl_sync(0xffffffffu, s, j);
            float4 v = hv[sj * 32 + lane];
            acc.x += v.x; acc.y += v.y; acc.z += v.z; acc.w += v.w;
        }
    }
    float e = 1.0f + epsp[layer];
    float4 self = hv[node * 32 + lane];
    acc.x += e * self.x; acc.y += e * self.y;
    acc.z += e * self.z; acc.w += e * self.w;
    uint32_t h01, l01, h23, l23;
    pack2(acc.x, acc.y, h01, l01);
    pack2(acc.z, acc.w, h23, l23);
    ((uint2*)g_zhi)[node * 32 + lane] = make_uint2(h01, h23);
    ((uint2*)g_zlo)[node * 32 + lane] = make_uint2(l01, l23);
}

// ---------------- MLP via bf16 mma.sync (pre-split operands, pure-copy fills) ----
#define T_BYTES (HID * STR * 2)        // 34816 per tile
#define OFF_AHI 0
#define OFF_ALO (T_BYTES)
#define OFF_BHI (2 * T_BYTES)
#define OFF_BLO (3 * T_BYTES)
#define SMEM_MMA (4 * T_BYTES)

__device__ __forceinline__ uint32_t smem_u32(const void* p) {
    uint32_t a;
    asm("{ .reg .u64 t; cvta.to.shared.u64 t, %1; cvt.u32.u64 %0, t; }" : "=r"(a) : "l"(p));
    return a;
}

#define LDSM_X4(r0, r1, r2, r3, a)                                                 \
    asm volatile("ldmatrix.sync.aligned.m8n8.x4.shared.b16 {%0,%1,%2,%3}, [%4];"   \
        : "=r"(r0), "=r"(r1), "=r"(r2), "=r"(r3) : "r"(a))
#define LDSM_X4T(r0, r1, r2, r3, a)                                                \
    asm volatile("ldmatrix.sync.aligned.m8n8.x4.trans.shared.b16 {%0,%1,%2,%3}, [%4];" \
        : "=r"(r0), "=r"(r1), "=r"(r2), "=r"(r3) : "r"(a))
#define MMA16816(d, a, b0, b1)                                                     \
    asm volatile("mma.sync.aligned.m16n8k16.row.col.f32.bf16.bf16.f32 "            \
        "{%0,%1,%2,%3},{%4,%5,%6,%7},{%8,%9},{%0,%1,%2,%3};"                       \
        : "+f"((d)[0]), "+f"((d)[1]), "+f"((d)[2]), "+f"((d)[3])                   \
        : "r"((a)[0]), "r"((a)[1]), "r"((a)[2]), "r"((a)[3]), "r"(b0), "r"(b1))

// copy A tile (z hi/lo) from global packed rows (256B/row) into STR-strided smem
__device__ __forceinline__ void copy_A(char* smem, int rowBase, int tid) {
    const uint2* shi = (const uint2*)g_zhi;
    const uint2* slo = (const uint2*)g_zlo;
    for (int i = tid; i < 128 * 32; i += 256) {
        int r = i >> 5, c2 = i & 31;          // uint2 units (8B), 32 per row
        int gr = rowBase + r;
        uint2 vh = make_uint2(0u, 0u), vl = make_uint2(0u, 0u);
        if (gr < N_NODES) {
            vh = shi[gr * 32 + c2];
            vl = slo[gr * 32 + c2];
        }
        uint32_t boff = (uint32_t)(r * STR) * 2 + c2 * 8;
        *(uint2*)(smem + OFF_AHI + boff) = vh;
        *(uint2*)(smem + OFF_ALO + boff) = vl;
    }
}

// copy pre-split W tile (already STR layout) into smem B
__device__ __forceinline__ void copy_W(char* smem, int widx, int tid) {
    const uint4* shi = (const uint4*)(g_whi + (size_t)widx * WT_ELEMS);
    const uint4* slo = (const uint4*)(g_wlo + (size_t)widx * WT_ELEMS);
    uint4* dhi = (uint4*)(smem + OFF_BHI);
    uint4* dlo = (uint4*)(smem + OFF_BLO);
    for (int i = tid; i < T_BYTES / 16; i += 256) {
        dhi[i] = shi[i];
        dlo[i] = slo[i];
    }
}

// D[128x128] += A[128x128] @ B[128x128] (B K-major, ldmatrix.trans)
__device__ __forceinline__ void gemm_mma(uint32_t sb, int warpM, int lane,
                                         float acc[16][4]) {
    const int lr = lane & 7, lj = lane >> 3;
    const uint32_t aOff = (uint32_t)((warpM + ((lj & 1) << 3) + lr) * STR
                                     + ((lj >> 1) << 3)) * 2;
    const uint32_t bRowPart = (uint32_t)((((lj >> 1) << 3) + lr) * STR
                                         + ((lj & 1) << 3)) * 2;
#pragma unroll 2
    for (int kt = 0; kt < 8; kt++) {
        uint32_t ah[4], al[4];
        uint32_t aAddr = sb + OFF_AHI + aOff + kt * 32;
        LDSM_X4(ah[0], ah[1], ah[2], ah[3], aAddr);
        LDSM_X4(al[0], al[1], al[2], al[3], aAddr + (OFF_ALO - OFF_AHI));
        uint32_t bBase = sb + OFF_BHI + bRowPart + (uint32_t)(kt * 16 * STR) * 2;
#pragma unroll
        for (int q = 0; q < 8; q++) {
            uint32_t bh[4], bl[4];
            uint32_t bAddr = bBase + q * 32;
            LDSM_X4T(bh[0], bh[1], bh[2], bh[3], bAddr);
            LDSM_X4T(bl[0], bl[1], bl[2], bl[3], bAddr + (OFF_BLO - OFF_BHI));
            MMA16816(acc[2 * q],     ah, bh[0], bh[2]);
            MMA16816(acc[2 * q],     ah, bl[0], bl[2]);
            MMA16816(acc[2 * q],     al, bh[0], bh[2]);
            MMA16816(acc[2 * q + 1], ah, bh[1], bh[3]);
            MMA16816(acc[2 * q + 1], ah, bl[1], bl[3]);
            MMA16816(acc[2 * q + 1], al, bh[1], bh[3]);
        }
    }
}

__global__ void __launch_bounds__(256, 1)
k_mlp_mma(int layer,
          const float* __restrict__ b1, const float* __restrict__ b2,
          const float* __restrict__ gamma, const float* __restrict__ beta,
          const float* __restrict__ mu, const float* __restrict__ var) {
    extern __shared__ __align__(16) char smem[];
    const uint32_t sb = smem_u32(smem);
    const int tid = threadIdx.x;
    const int warp = tid >> 5, lane = tid & 31;
    const int warpM = warp * 16;
    const int rowBase = blockIdx.x * 128;

    copy_A(smem, rowBase, tid);
    copy_W(smem, layer * 2 + 0, tid);     // W1
    __syncthreads();

    float acc[16][4];
#pragma unroll
    for (int p = 0; p < 16; p++)
#pragma unroll
        for (int j = 0; j < 4; j++) acc[p][j] = 0.f;
    gemm_mma(sb, warpM, lane, acc);

    // mid epilogue: relu(acc + b1) -> rewrite OWN A rows (warp reads only own rows)
    {
        const int r = lane >> 2, cB = (lane & 3) * 2;
        const int row0 = warpM + r, row1 = row0 + 8;
#pragma unroll
        for (int p = 0; p < 16; p++) {
            int c = p * 8 + cB;
            float2 bb = __ldg((const float2*)&b1[c]);
            uint32_t h, l;
            pack2(fmaxf(acc[p][0] + bb.x, 0.f), fmaxf(acc[p][1] + bb.y, 0.f), h, l);
            *(uint32_t*)(smem + OFF_AHI + (row0 * STR + c) * 2) = h;
            *(uint32_t*)(smem + OFF_ALO + (row0 * STR + c) * 2) = l;
            pack2(fmaxf(acc[p][2] + bb.x, 0.f), fmaxf(acc[p][3] + bb.y, 0.f), h, l);
            *(uint32_t*)(smem + OFF_AHI + (row1 * STR + c) * 2) = h;
            *(uint32_t*)(smem + OFF_ALO + (row1 * STR + c) * 2) = l;
        }
    }
    __syncthreads();                       // everyone done reading B(W1)
    copy_W(smem, layer * 2 + 1, tid);      // W2
    __syncthreads();

#pragma unroll
    for (int p = 0; p < 16; p++)
#pragma unroll
        for (int j = 0; j < 4; j++) acc[p][j] = 0.f;
    gemm_mma(sb, warpM, lane, acc);

    // final epilogue: bias2 + relu + BN -> g_h
    {
        const int r = lane >> 2, cB = (lane & 3) * 2;
        const int gr0 = rowBase + warpM + r, gr1 = gr0 + 8;
#pragma unroll
        for (int p = 0; p < 16; p++) {
            int c = p * 8 + cB;
            float2 bb = __ldg((const float2*)&b2[c]);
            float2 gm = __ldg((const float2*)&gamma[c]);
            float2 vr = __ldg((const float2*)&var[c]);
            float2 mm = __ldg((const float2*)&mu[c]);
            float2 be = __ldg((const float2*)&beta[c]);
            float sc0 = gm.x * rsqrtf(vr.x + BN_EPS);
            float sc1 = gm.y * rsqrtf(vr.y + BN_EPS);
            float sh0 = be.x - mm.x * sc0;
            float sh1 = be.y - mm.y * sc1;
            if (gr0 < N_NODES) {
                float o0 = fmaxf(acc[p][0] + bb.x, 0.f) * sc0 + sh0;
                float o1 = fmaxf(acc[p][1] + bb.y, 0.f) * sc1 + sh1;
                *(float2*)&g_h[(size_t)gr0 * HID + c] = make_float2(o0, o1);
            }
            if (gr1 < N_NODES) {
                float o0 = fmaxf(acc[p][2] + bb.x, 0.f) * sc0 + sh0;
                float o1 = fmaxf(acc[p][3] + bb.y, 0.f) * sc1 + sh1;
                *(float2*)&g_h[(size_t)gr1 * HID + c] = make_float2(o0, o1);
            }
        }
    }
}

// ---------------- pooling ----------------
__global__ void k_pool(const int* __restrict__ batch) {
    int idx = blockIdx.x * blockDim.x + threadIdx.x;
    int node = idx >> 5, lane = idx & 31;
    if (node >= N_NODES) return;
    int b = batch[node];
    float4 v = ((const float4*)g_h)[node * 32 + lane];
    float* p = &g_pool[b * HID + lane * 4];
    atomicAdd(p + 0, v.x);
    atomicAdd(p + 1, v.y);
    atomicAdd(p + 2, v.z);
    atomicAdd(p + 3, v.w);
    if (lane == 0) atomicAdd(&g_cnt[b], 1.0f);
}

// ---------------- head ----------------
__global__ void k_head(const float* __restrict__ l1w, const float* __restrict__ l1b,
                       const float* __restrict__ l2w, const float* __restrict__ l2b,
                       float* __restrict__ out) {
    __shared__ float p[HID], q[HID], r[N_CLASSES];
    int g = blockIdx.x, tid = threadIdx.x;
    float cnt = fmaxf(g_cnt[g], 1.0f);
    p[tid] = g_pool[g * HID + tid] / cnt;
    __syncthreads();
    float acc = l1b[tid];
    for (int k = 0; k < HID; k++) acc += p[k] * l1w[k * HID + tid];
    q[tid] = fmaxf(acc, 0.f);
    __syncthreads();
    if (tid < N_CLASSES) {
        float a2 = l2b[tid];
        for (int k = 0; k < HID; k++) a2 += q[k] * l2w[k * N_CLASSES + tid];
        r[tid] = a2;
    }
    __syncthreads();
    if (tid < N_CLASSES) {
        float m = -INFINITY;
        for (int j = 0; j < N_CLASSES; j++) m = fmaxf(m, r[j]);
        float s = 0.f;
        for (int j = 0; j < N_CLASSES; j++) s += expf(r[j] - m);
        out[g * N_CLASSES + tid] = r[tid] - m - logf(s);
    }
}

// ---------------- launch ----------------
extern "C" void kernel_launch(void* const* d_in, const int* in_sizes, int n_in,
                              void* d_out, int out_size) {
    const float* x        = (const float*)d_in[0];
    const int*   eidx     = (const int*)d_in[1];
    const int*   batch    = (const int*)d_in[2];
    const float* W1       = (const float*)d_in[3];
    const float* b1       = (const float*)d_in[4];
    const float* W2       = (const float*)d_in[5];
    const float* b2       = (const float*)d_in[6];
    const float* gamma    = (const float*)d_in[7];
    const float* beta     = (const float*)d_in[8];
    const float* bn_mean  = (const float*)d_in[9];
    const float* bn_var   = (const float*)d_in[10];
    const float* eps      = (const float*)d_in[11];
    const float* lin1_w   = (const float*)d_in[12];
    const float* lin1_b   = (const float*)d_in[13];
    const float* lin2_w   = (const float*)d_in[14];
    const float* lin2_b   = (const float*)d_in[15];
    float* out = (float*)d_out;

    const int* src = eidx;
    const int* dst = eidx + N_EDGES;

    cudaFuncSetAttribute(k_mlp_mma, cudaFuncAttributeMaxDynamicSharedMemorySize, SMEM_MMA);

    k_zero<<<(N_NODES + 255) / 256, 256>>>();
    k_hist<<<(N_EDGES + 255) / 256, 256>>>(dst);
    k_scan<<<1, 1024>>>();
    k_scatter<<<(N_EDGES + 255) / 256, 256>>>(src, dst);
    k_wsplit<<<(3 * 2 * HID * HID + 255) / 256, 256>>>(W1, W2);

    const int nblk = (N_NODES + 127) / 128;
    for (int l = 0; l < 3; l++) {
        k_agg<<<(N_NODES * 32 + 255) / 256, 256>>>(x, l, eps);
        k_mlp_mma<<<nblk, 256, SMEM_MMA>>>(
            l, b1 + l * HID, b2 + l * HID,
            gamma + l * HID, beta + l * HID,
            bn_mean + l * HID, bn_var + l * HID);
    }

    k_pool<<<(N_NODES * 32 + 255) / 256, 256>>>(batch);
    k_head<<<N_GRAPHS, HID>>>(lin1_w, lin1_b, lin2_w, lin2_b, out);
}

// round 9
// speedup vs baseline: 1.5100x; 1.2757x over previous
#include <cuda_runtime.h>
#include <cuda_bf16.h>
#include <math.h>
#include <stdint.h>

#define N_NODES  100000
#define N_EDGES  3200000
#define HID      128
#define N_GRAPHS 512
#define N_CLASSES 10
#define BN_EPS   1e-5f

// ---------------- scratch (device globals; no allocations) ----------------
__device__ float g_h[N_NODES * HID];
__device__ __nv_bfloat16 g_zhi[N_NODES * HID];   // aggregated z, bf16 hi
__device__ __nv_bfloat16 g_zlo[N_NODES * HID];   // aggregated z, bf16 lo (residual)
__device__ int   g_deg[N_NODES];
__device__ int   g_off[N_NODES + 1];
__device__ int   g_cur[N_NODES];
__device__ int   g_csr[N_EDGES];
__device__ float g_pool[N_GRAPHS * HID];         // holds per-graph MEAN

#define STR   136                      // bf16 row stride in smem (272B, 16B-aligned)
#define WT_ELEMS (HID * STR)
__device__ __nv_bfloat16 g_whi[3 * 2 * WT_ELEMS];
__device__ __nv_bfloat16 g_wlo[3 * 2 * WT_ELEMS];

// ---------------- CSR build ----------------
__global__ void k_zero() {
    int i = blockIdx.x * blockDim.x + threadIdx.x;
    if (i < N_NODES) g_deg[i] = 0;
}

__global__ void k_hist(const int* __restrict__ dst) {
    int e = blockIdx.x * blockDim.x + threadIdx.x;
    if (e < N_EDGES) atomicAdd(&g_deg[dst[e]], 1);
}

__global__ void k_scan() {
    __shared__ int warpsum[32];
    const int tid = threadIdx.x;
    const int C = (N_NODES + 1023) / 1024;
    const int beg = tid * C;
    const int end = min(beg + C, N_NODES);
    int sum = 0;
    for (int i = beg; i < end; i++) sum += g_deg[i];
    int lane = tid & 31, wid = tid >> 5;
    int v = sum;
#pragma unroll
    for (int d = 1; d < 32; d <<= 1) {
        int t = __shfl_up_sync(0xffffffffu, v, d);
        if (lane >= d) v += t;
    }
    if (lane == 31) warpsum[wid] = v;
    __syncthreads();
    if (wid == 0) {
        int w = warpsum[lane];
#pragma unroll
        for (int d = 1; d < 32; d <<= 1) {
            int t = __shfl_up_sync(0xffffffffu, w, d);
            if (lane >= d) w += t;
        }
        warpsum[lane] = w;
    }
    __syncthreads();
    int excl = v - sum + (wid > 0 ? warpsum[wid - 1] : 0);
    int run = excl;
    for (int i = beg; i < end; i++) {
        int d = g_deg[i];
        g_off[i] = run;
        g_cur[i] = run;
        run += d;
    }
    if (tid == 1023) g_off[N_NODES] = run;
}

__global__ void k_scatter(const int* __restrict__ src, const int* __restrict__ dst) {
    int e = blockIdx.x * blockDim.x + threadIdx.x;
    if (e < N_EDGES) {
        int pos = atomicAdd(&g_cur[dst[e]], 1);
        g_csr[pos] = src[e];
    }
}

// ---------------- bf16 split helpers ----------------
__device__ __forceinline__ void pack2(float v0, float v1, uint32_t& hi, uint32_t& lo) {
    uint32_t h;
    asm("cvt.rn.bf16x2.f32 %0, %1, %2;" : "=r"(h) : "f"(v1), "f"(v0));
    float h0 = __uint_as_float(h << 16);
    float h1 = __uint_as_float(h & 0xffff0000u);
    asm("cvt.rn.bf16x2.f32 %0, %1, %2;" : "=r"(lo) : "f"(v1 - h1), "f"(v0 - h0));
    hi = h;
}

// ---------------- weight pre-split (once per call) ----------------
__global__ void k_wsplit(const float* __restrict__ W1, const float* __restrict__ W2) {
    int i = blockIdx.x * blockDim.x + threadIdx.x;
    if (i >= 3 * 2 * HID * HID) return;
    int l = i / (2 * HID * HID);
    int rem = i % (2 * HID * HID);
    int m = rem / (HID * HID);
    int kn = rem % (HID * HID);
    int k = kn >> 7, n = kn & 127;
    float v = (m ? W2 : W1)[l * HID * HID + kn];
    __nv_bfloat16 hb = __float2bfloat16(v);
    __nv_bfloat16 lb = __float2bfloat16(v - __bfloat162float(hb));
    int o = (l * 2 + m) * WT_ELEMS + k * STR + n;
    g_whi[o] = hb;
    g_wlo[o] = lb;
}

// ---------------- aggregation: z packed to bf16 hi/lo ----------------
__global__ void k_agg(const float* __restrict__ x, int layer, const float* __restrict__ epsp) {
    int node = (blockIdx.x * blockDim.x + threadIdx.x) >> 5;
    int lane = threadIdx.x & 31;
    if (node >= N_NODES) return;
    const float* hin = (layer == 0) ? x : (const float*)g_h;
    const float4* hv = (const float4*)hin;
    int beg = g_off[node], end = g_off[node + 1];
    float4 acc = make_float4(0.f, 0.f, 0.f, 0.f);
    for (int base = beg; base < end; base += 32) {
        int n = min(32, end - base);
        int s = (lane < n) ? g_csr[base + lane] : 0;
#pragma unroll 4
        for (int j = 0; j < n; j++) {
            int sj = __shfl_sync(0xffffffffu, s, j);
            float4 v = hv[sj * 32 + lane];
            acc.x += v.x; acc.y += v.y; acc.z += v.z; acc.w += v.w;
        }
    }
    float e = 1.0f + epsp[layer];
    float4 self = hv[node * 32 + lane];
    acc.x += e * self.x; acc.y += e * self.y;
    acc.z += e * self.z; acc.w += e * self.w;
    uint32_t h01, l01, h23, l23;
    pack2(acc.x, acc.y, h01, l01);
    pack2(acc.z, acc.w, h23, l23);
    ((uint2*)g_zhi)[node * 32 + lane] = make_uint2(h01, h23);
    ((uint2*)g_zlo)[node * 32 + lane] = make_uint2(l01, l23);
}

// ---------------- MLP: bf16 mma.sync + full cp.async prefetch ----------------
#define T_BYTES (HID * STR * 2)        // 34816 per tile
#define OFF_AHI 0
#define OFF_ALO (T_BYTES)
#define OFF_W1HI (2 * T_BYTES)
#define OFF_W1LO (3 * T_BYTES)
#define OFF_W2HI (4 * T_BYTES)
#define OFF_W2LO (5 * T_BYTES)
#define SMEM_MMA (6 * T_BYTES)         // 208896 B

__device__ __forceinline__ uint32_t smem_u32(const void* p) {
    uint32_t a;
    asm("{ .reg .u64 t; cvta.to.shared.u64 t, %1; cvt.u32.u64 %0, t; }" : "=r"(a) : "l"(p));
    return a;
}

#define CP16(dst, src)                                                             \
    asm volatile("cp.async.cg.shared.global [%0], [%1], 16;" :: "r"(dst), "l"(src))
#define CP16P(dst, src, nbytes)                                                    \
    asm volatile("cp.async.cg.shared.global [%0], [%1], 16, %2;"                   \
                 :: "r"(dst), "l"(src), "r"(nbytes))
#define CP_COMMIT() asm volatile("cp.async.commit_group;" ::: "memory")
#define CP_WAIT(n)  asm volatile("cp.async.wait_group %0;" :: "n"(n) : "memory")

#define LDSM_X4(r0, r1, r2, r3, a)                                                 \
    asm volatile("ldmatrix.sync.aligned.m8n8.x4.shared.b16 {%0,%1,%2,%3}, [%4];"   \
        : "=r"(r0), "=r"(r1), "=r"(r2), "=r"(r3) : "r"(a))
#define LDSM_X4T(r0, r1, r2, r3, a)                                                \
    asm volatile("ldmatrix.sync.aligned.m8n8.x4.trans.shared.b16 {%0,%1,%2,%3}, [%4];" \
        : "=r"(r0), "=r"(r1), "=r"(r2), "=r"(r3) : "r"(a))
#define MMA16816(d, a, b0, b1)                                                     \
    asm volatile("mma.sync.aligned.m16n8k16.row.col.f32.bf16.bf16.f32 "            \
        "{%0,%1,%2,%3},{%4,%5,%6,%7},{%8,%9},{%0,%1,%2,%3};"                       \
        : "+f"((d)[0]), "+f"((d)[1]), "+f"((d)[2]), "+f"((d)[3])                   \
        : "r"((a)[0]), "r"((a)[1]), "r"((a)[2]), "r"((a)[3]), "r"(b0), "r"(b1))

// D[128x(128)] += A @ B; B hi at bOff, lo at bOff + T_BYTES
__device__ __forceinline__ void gemm_mma(uint32_t sb, uint32_t bOff, int warpM,
                                         int lane, float acc[16][4]) {
    const int lr = lane & 7, lj = lane >> 3;
    const uint32_t aOff = (uint32_t)((warpM + ((lj & 1) << 3) + lr) * STR
                                     + ((lj >> 1) << 3)) * 2;
    const uint32_t bRowPart = (uint32_t)((((lj >> 1) << 3) + lr) * STR
                                         + ((lj & 1) << 3)) * 2;
#pragma unroll 2
    for (int kt = 0; kt < 8; kt++) {
        uint32_t ah[4], al[4];
        uint32_t aAddr = sb + OFF_AHI + aOff + kt * 32;
        LDSM_X4(ah[0], ah[1], ah[2], ah[3], aAddr);
        LDSM_X4(al[0], al[1], al[2], al[3], aAddr + (OFF_ALO - OFF_AHI));
        uint32_t bBase = sb + bOff + bRowPart + (uint32_t)(kt * 16 * STR) * 2;
#pragma unroll
        for (int q = 0; q < 8; q++) {
            uint32_t bh[4], bl[4];
            uint32_t bAddr = bBase + q * 32;
            LDSM_X4T(bh[0], bh[1], bh[2], bh[3], bAddr);
            LDSM_X4T(bl[0], bl[1], bl[2], bl[3], bAddr + T_BYTES);
            MMA16816(acc[2 * q],     ah, bh[0], bh[2]);
            MMA16816(acc[2 * q],     ah, bl[0], bl[2]);
            MMA16816(acc[2 * q],     al, bh[0], bh[2]);
            MMA16816(acc[2 * q + 1], ah, bh[1], bh[3]);
            MMA16816(acc[2 * q + 1], ah, bl[1], bl[3]);
            MMA16816(acc[2 * q + 1], al, bh[1], bh[3]);
        }
    }
}

__global__ void __launch_bounds__(256, 1)
k_mlp_mma(int layer,
          const float* __restrict__ b1, const float* __restrict__ b2,
          const float* __restrict__ gamma, const float* __restrict__ beta,
          const float* __restrict__ mu, const float* __restrict__ var) {
    extern __shared__ __align__(16) char smem[];
    const uint32_t sb = smem_u32(smem);
    const int tid = threadIdx.x;
    const int warp = tid >> 5, lane = tid & 31;
    const int warpM = warp * 16;
    const int rowBase = blockIdx.x * 128;

    // ---- group 0: A (z hi/lo) + W1 ----
    {
        const char* ghi = (const char*)g_zhi;
        const char* glo = (const char*)g_zlo;
        // A: 128 rows x 16 chunks of 16B, hi and lo
        for (int i = tid; i < 128 * 16; i += 256) {
            int r = i >> 4, c = i & 15;
            int gr = rowBase + r;
            int ok = (gr < N_NODES);
            long goff = ok ? ((long)gr * 256 + c * 16) : 0;
            uint32_t soff = (uint32_t)(r * STR) * 2 + c * 16;
            uint32_t n = ok ? 16u : 0u;
            CP16P(sb + OFF_AHI + soff, ghi + goff, n);
            CP16P(sb + OFF_ALO + soff, glo + goff, n);
        }
        const char* whi = (const char*)(g_whi + (size_t)(layer * 2 + 0) * WT_ELEMS);
        const char* wlo = (const char*)(g_wlo + (size_t)(layer * 2 + 0) * WT_ELEMS);
        for (int i = tid; i < T_BYTES / 16; i += 256) {
            CP16(sb + OFF_W1HI + i * 16, whi + i * 16);
            CP16(sb + OFF_W1LO + i * 16, wlo + i * 16);
        }
    }
    CP_COMMIT();
    // ---- group 1: W2 ----
    {
        const char* whi = (const char*)(g_whi + (size_t)(layer * 2 + 1) * WT_ELEMS);
        const char* wlo = (const char*)(g_wlo + (size_t)(layer * 2 + 1) * WT_ELEMS);
        for (int i = tid; i < T_BYTES / 16; i += 256) {
            CP16(sb + OFF_W2HI + i * 16, whi + i * 16);
            CP16(sb + OFF_W2LO + i * 16, wlo + i * 16);
        }
    }
    CP_COMMIT();

    CP_WAIT(1);                 // A + W1 resident
    __syncthreads();

    float acc[16][4];
#pragma unroll
    for (int p = 0; p < 16; p++)
#pragma unroll
        for (int j = 0; j < 4; j++) acc[p][j] = 0.f;
    gemm_mma(sb, OFF_W1HI, warpM, lane, acc);

    // mid epilogue: relu(acc + b1) -> rewrite OWN A rows (each warp reads only own rows)
    {
        const int r = lane >> 2, cB = (lane & 3) * 2;
        const int row0 = warpM + r, row1 = row0 + 8;
#pragma unroll
        for (int p = 0; p < 16; p++) {
            int c = p * 8 + cB;
            float2 bb = __ldg((const float2*)&b1[c]);
            uint32_t h, l;
            pack2(fmaxf(acc[p][0] + bb.x, 0.f), fmaxf(acc[p][1] + bb.y, 0.f), h, l);
            *(uint32_t*)(smem + OFF_AHI + (row0 * STR + c) * 2) = h;
            *(uint32_t*)(smem + OFF_ALO + (row0 * STR + c) * 2) = l;
            pack2(fmaxf(acc[p][2] + bb.x, 0.f), fmaxf(acc[p][3] + bb.y, 0.f), h, l);
            *(uint32_t*)(smem + OFF_AHI + (row1 * STR + c) * 2) = h;
            *(uint32_t*)(smem + OFF_ALO + (row1 * STR + c) * 2) = l;
        }
    }
    CP_WAIT(0);                 // W2 resident
    __syncthreads();            // A rewrite + W2 visible to all

#pragma unroll
    for (int p = 0; p < 16; p++)
#pragma unroll
        for (int j = 0; j < 4; j++) acc[p][j] = 0.f;
    gemm_mma(sb, OFF_W2HI, warpM, lane, acc);

    // final epilogue: bias2 + relu + BN -> g_h
    {
        const int r = lane >> 2, cB = (lane & 3) * 2;
        const int gr0 = rowBase + warpM + r, gr1 = gr0 + 8;
#pragma unroll
        for (int p = 0; p < 16; p++) {
            int c = p * 8 + cB;
            float2 bb = __ldg((const float2*)&b2[c]);
            float2 gm = __ldg((const float2*)&gamma[c]);
            float2 vr = __ldg((const float2*)&var[c]);
            float2 mm = __ldg((const float2*)&mu[c]);
            float2 be = __ldg((const float2*)&beta[c]);
            float sc0 = gm.x * rsqrtf(vr.x + BN_EPS);
            float sc1 = gm.y * rsqrtf(vr.y + BN_EPS);
            float sh0 = be.x - mm.x * sc0;
            float sh1 = be.y - mm.y * sc1;
            if (gr0 < N_NODES) {
                float o0 = fmaxf(acc[p][0] + bb.x, 0.f) * sc0 + sh0;
                float o1 = fmaxf(acc[p][1] + bb.y, 0.f) * sc1 + sh1;
                *(float2*)&g_h[(size_t)gr0 * HID + c] = make_float2(o0, o1);
            }
            if (gr1 < N_NODES) {
                float o0 = fmaxf(acc[p][2] + bb.x, 0.f) * sc0 + sh0;
                float o1 = fmaxf(acc[p][3] + bb.y, 0.f) * sc1 + sh1;
                *(float2*)&g_h[(size_t)gr1 * HID + c] = make_float2(o0, o1);
            }
        }
    }
}

// ---------------- pooling: segment mean (batch sorted), no atomics ----------------
__global__ void k_pool_seg(const int* __restrict__ batch) {
    const int g = blockIdx.x;          // graph id
    const int tid = threadIdx.x;       // 128 threads, one per dim
    __shared__ int s_beg, s_end;
    if (tid == 0) {
        // lower_bound(batch, g) and lower_bound(batch, g+1)
        int lo = 0, hi = N_NODES;
        while (lo < hi) { int m = (lo + hi) >> 1; if (batch[m] < g) lo = m + 1; else hi = m; }
        s_beg = lo;
        lo = s_beg; hi = N_NODES;
        while (lo < hi) { int m = (lo + hi) >> 1; if (batch[m] < g + 1) lo = m + 1; else hi = m; }
        s_end = lo;
    }
    __syncthreads();
    int beg = s_beg, end = s_end;
    float acc = 0.f;
    for (int r = beg; r < end; r++) acc += g_h[(size_t)r * HID + tid];
    float cnt = (float)(end - beg);
    g_pool[g * HID + tid] = (cnt > 0.f) ? (acc / cnt) : 0.f;
}

// ---------------- head ----------------
__global__ void k_head(const float* __restrict__ l1w, const float* __restrict__ l1b,
                       const float* __restrict__ l2w, const float* __restrict__ l2b,
                       float* __restrict__ out) {
    __shared__ float p[HID], q[HID], r[N_CLASSES];
    int g = blockIdx.x, tid = threadIdx.x;
    p[tid] = g_pool[g * HID + tid];    // already mean
    __syncthreads();
    float acc = l1b[tid];
    for (int k = 0; k < HID; k++) acc += p[k] * l1w[k * HID + tid];
    q[tid] = fmaxf(acc, 0.f);
    __syncthreads();
    if (tid < N_CLASSES) {
        float a2 = l2b[tid];
        for (int k = 0; k < HID; k++) a2 += q[k] * l2w[k * N_CLASSES + tid];
        r[tid] = a2;
    }
    __syncthreads();
    if (tid < N_CLASSES) {
        float m = -INFINITY;
        for (int j = 0; j < N_CLASSES; j++) m = fmaxf(m, r[j]);
        float s = 0.f;
        for (int j = 0; j < N_CLASSES; j++) s += expf(r[j] - m);
        out[g * N_CLASSES + tid] = r[tid] - m - logf(s);
    }
}

// ---------------- launch ----------------
extern "C" void kernel_launch(void* const* d_in, const int* in_sizes, int n_in,
                              void* d_out, int out_size) {
    const float* x        = (const float*)d_in[0];
    const int*   eidx     = (const int*)d_in[1];
    const int*   batch    = (const int*)d_in[2];
    const float* W1       = (const float*)d_in[3];
    const float* b1       = (const float*)d_in[4];
    const float* W2       = (const float*)d_in[5];
    const float* b2       = (const float*)d_in[6];
    const float* gamma    = (const float*)d_in[7];
    const float* beta     = (const float*)d_in[8];
    const float* bn_mean  = (const float*)d_in[9];
    const float* bn_var   = (const float*)d_in[10];
    const float* eps      = (const float*)d_in[11];
    const float* lin1_w   = (const float*)d_in[12];
    const float* lin1_b   = (const float*)d_in[13];
    const float* lin2_w   = (const float*)d_in[14];
    const float* lin2_b   = (const float*)d_in[15];
    float* out = (float*)d_out;

    const int* src = eidx;
    const int* dst = eidx + N_EDGES;

    cudaFuncSetAttribute(k_mlp_mma, cudaFuncAttributeMaxDynamicSharedMemorySize, SMEM_MMA);

    k_zero<<<(N_NODES + 255) / 256, 256>>>();
    k_hist<<<(N_EDGES + 255) / 256, 256>>>(dst);
    k_scan<<<1, 1024>>>();
    k_scatter<<<(N_EDGES + 255) / 256, 256>>>(src, dst);
    k_wsplit<<<(3 * 2 * HID * HID + 255) / 256, 256>>>(W1, W2);

    const int nblk = (N_NODES + 127) / 128;
    for (int l = 0; l < 3; l++) {
        k_agg<<<(N_NODES * 32 + 255) / 256, 256>>>(x, l, eps);
        k_mlp_mma<<<nblk, 256, SMEM_MMA>>>(
            l, b1 + l * HID, b2 + l * HID,
            gamma + l * HID, beta + l * HID,
            bn_mean + l * HID, bn_var + l * HID);
    }

    k_pool_seg<<<N_GRAPHS, HID>>>(batch);
    k_head<<<N_GRAPHS, HID>>>(lin1_w, lin1_b, lin2_w, lin2_b, out);
}